// round 2
// baseline (speedup 1.0000x reference)
#include <cuda_runtime.h>
#include <cuda_bf16.h>

// Problem constants
constexpr int DIMC  = 512;                 // head dim == block_len
constexpr int ROWS  = 4 * 16 * 512;        // 32768 total rows
constexpr int NBLK  = 4 * 16;              // 64 attention blocks

// Scratch (device globals: allocation-free per harness rules)
__device__ float g_Q[(size_t)ROWS * DIMC];
__device__ float g_K[(size_t)ROWS * DIMC];
__device__ float g_V[(size_t)ROWS * DIMC];
__device__ float g_S[(size_t)ROWS * DIMC];  // scores then probabilities
__device__ float g_O[(size_t)ROWS * DIMC];  // attention out + residual

// ---------------------------------------------------------------------------
// 128x128x512 fp32 GEMM tile: 256 threads, 8x8 micro-tile per thread, BK=8.
// A is [128 x 512] row-major (lda=512).
// TRANSB=false: B is [512 x >=128] row-major (ldb=512), tile starts at col 0 of B ptr.
// TRANSB=true : B is [128 x 512] row-major (ldb=512): C[i][j] = sum_k A[i,k]*B[j,k].
// ---------------------------------------------------------------------------
template<bool TRANSB>
__device__ __forceinline__ void gemm_tile(const float* __restrict__ A,
                                          const float* __restrict__ B,
                                          float (&acc)[8][8])
{
    __shared__ float As[8][128];
    __shared__ float Bs[8][128];

    const int tid = threadIdx.x;
    const int ar  = tid >> 1;          // 0..127
    const int ac  = (tid & 1) * 4;     // 0 or 4
    const int tr  = tid >> 4;          // 0..15
    const int tc  = tid & 15;          // 0..15

    for (int k0 = 0; k0 < DIMC; k0 += 8) {
        // Load A tile (128 rows x 8 k), transpose into As[k][m]
        float4 av = *reinterpret_cast<const float4*>(A + (size_t)ar * DIMC + k0 + ac);
        As[ac + 0][ar] = av.x;
        As[ac + 1][ar] = av.y;
        As[ac + 2][ar] = av.z;
        As[ac + 3][ar] = av.w;

        if (TRANSB) {
            // B tile: 128 n-rows x 8 k, transpose into Bs[k][n]
            float4 bv = *reinterpret_cast<const float4*>(B + (size_t)ar * DIMC + k0 + ac);
            Bs[ac + 0][ar] = bv.x;
            Bs[ac + 1][ar] = bv.y;
            Bs[ac + 2][ar] = bv.z;
            Bs[ac + 3][ar] = bv.w;
        } else {
            // B tile: 8 k-rows x 128 n
            const int br = tid >> 5;          // 0..7
            const int bc = (tid & 31) * 4;    // 0..124
            float4 bv = *reinterpret_cast<const float4*>(B + (size_t)(k0 + br) * DIMC + bc);
            *reinterpret_cast<float4*>(&Bs[br][bc]) = bv;
        }
        __syncthreads();

        #pragma unroll
        for (int k = 0; k < 8; k++) {
            float a[8], b[8];
            #pragma unroll
            for (int i = 0; i < 8; i++) a[i] = As[k][tr * 8 + i];
            #pragma unroll
            for (int j = 0; j < 8; j++) b[j] = Bs[k][tc * 8 + j];
            #pragma unroll
            for (int i = 0; i < 8; i++)
                #pragma unroll
                for (int j = 0; j < 8; j++)
                    acc[i][j] += a[i] * b[j];
        }
        __syncthreads();
    }
}

// ---------------------------------------------------------------------------
// K1: Q/K/V = X @ W{1,2,3} + b{1,2,3}.  grid = (4, 256, 3), block = 256
// ---------------------------------------------------------------------------
__global__ __launch_bounds__(256)
void qkv_kernel(const float* __restrict__ X,
                const float* __restrict__ W1, const float* __restrict__ W2, const float* __restrict__ W3,
                const float* __restrict__ B1, const float* __restrict__ B2, const float* __restrict__ B3)
{
    const float* W    = (blockIdx.z == 0) ? W1 : (blockIdx.z == 1) ? W2 : W3;
    const float* bias = (blockIdx.z == 0) ? B1 : (blockIdx.z == 1) ? B2 : B3;
    float*       C    = (blockIdx.z == 0) ? g_Q : (blockIdx.z == 1) ? g_K : g_V;

    const int row0 = blockIdx.y * 128;
    const int col0 = blockIdx.x * 128;

    float acc[8][8] = {};
    gemm_tile<false>(X + (size_t)row0 * DIMC, W + col0, acc);

    const int tr = threadIdx.x >> 4, tc = threadIdx.x & 15;
    #pragma unroll
    for (int i = 0; i < 8; i++) {
        const size_t rbase = (size_t)(row0 + tr * 8 + i) * DIMC + col0 + tc * 8;
        #pragma unroll
        for (int j = 0; j < 8; j++)
            C[rbase + j] = acc[i][j] + bias[col0 + tc * 8 + j];
    }
}

// ---------------------------------------------------------------------------
// K2: S = (Q @ K^T) * scale + (1 - mask) * (-1e10), per attention block.
// grid = (4, 4, 64), block = 256
// ---------------------------------------------------------------------------
__global__ __launch_bounds__(256)
void score_kernel(const float* __restrict__ mask)
{
    const int bn = blockIdx.z;
    const int q0 = blockIdx.y * 128;
    const int k0 = blockIdx.x * 128;

    const float* A = g_Q + (size_t)bn * DIMC * DIMC + (size_t)q0 * DIMC;
    const float* B = g_K + (size_t)bn * DIMC * DIMC + (size_t)k0 * DIMC;

    float acc[8][8] = {};
    gemm_tile<true>(A, B, acc);

    const float scale = 0.04419417382415922f;  // 1/sqrt(512)
    const int tr = threadIdx.x >> 4, tc = threadIdx.x & 15;
    #pragma unroll
    for (int i = 0; i < 8; i++) {
        const size_t rbase = ((size_t)bn * DIMC + q0 + tr * 8 + i) * DIMC + k0 + tc * 8;
        #pragma unroll
        for (int j = 0; j < 8; j++) {
            float m = mask[rbase + j];
            g_S[rbase + j] = acc[i][j] * scale + (1.0f - m) * (-1e10f);
        }
    }
}

// ---------------------------------------------------------------------------
// Block reductions (256 threads = 8 warps)
// ---------------------------------------------------------------------------
__device__ __forceinline__ float block_sum(float v)
{
    __shared__ float sb[8];
    const int lane = threadIdx.x & 31, w = threadIdx.x >> 5;
    #pragma unroll
    for (int o = 16; o; o >>= 1) v += __shfl_xor_sync(0xffffffffu, v, o);
    if (lane == 0) sb[w] = v;
    __syncthreads();
    if (w == 0) {
        float r = (lane < 8) ? sb[lane] : 0.0f;
        #pragma unroll
        for (int o = 4; o; o >>= 1) r += __shfl_xor_sync(0xffffffffu, r, o);
        if (lane == 0) sb[0] = r;
    }
    __syncthreads();
    float r = sb[0];
    __syncthreads();
    return r;
}

__device__ __forceinline__ float block_max(float v)
{
    __shared__ float sm[8];
    const int lane = threadIdx.x & 31, w = threadIdx.x >> 5;
    #pragma unroll
    for (int o = 16; o; o >>= 1) v = fmaxf(v, __shfl_xor_sync(0xffffffffu, v, o));
    if (lane == 0) sm[w] = v;
    __syncthreads();
    if (w == 0) {
        float r = (lane < 8) ? sm[lane] : -3.4e38f;
        #pragma unroll
        for (int o = 4; o; o >>= 1) r = fmaxf(r, __shfl_xor_sync(0xffffffffu, r, o));
        if (lane == 0) sm[0] = r;
    }
    __syncthreads();
    float r = sm[0];
    __syncthreads();
    return r;
}

// ---------------------------------------------------------------------------
// K3: row softmax over g_S, in place. grid = 32768, block = 256
// ---------------------------------------------------------------------------
__global__ __launch_bounds__(256)
void softmax_kernel()
{
    const size_t base = (size_t)blockIdx.x * DIMC;
    const int t = threadIdx.x;
    float v0 = g_S[base + t];
    float v1 = g_S[base + t + 256];
    float mx = block_max(fmaxf(v0, v1));
    float e0 = __expf(v0 - mx);
    float e1 = __expf(v1 - mx);
    float inv = 1.0f / block_sum(e0 + e1);
    g_S[base + t]       = e0 * inv;
    g_S[base + t + 256] = e1 * inv;
}

// ---------------------------------------------------------------------------
// K4: O = P @ V + X (residual). grid = (4, 4, 64), block = 256
// ---------------------------------------------------------------------------
__global__ __launch_bounds__(256)
void out_kernel(const float* __restrict__ X)
{
    const int bn = blockIdx.z;
    const int m0 = blockIdx.y * 128;
    const int n0 = blockIdx.x * 128;

    const float* A = g_S + (size_t)bn * DIMC * DIMC + (size_t)m0 * DIMC;
    const float* B = g_V + (size_t)bn * DIMC * DIMC + n0;

    float acc[8][8] = {};
    gemm_tile<false>(A, B, acc);

    const int tr = threadIdx.x >> 4, tc = threadIdx.x & 15;
    #pragma unroll
    for (int i = 0; i < 8; i++) {
        const size_t rbase = ((size_t)bn * DIMC + m0 + tr * 8 + i) * DIMC + n0 + tc * 8;
        #pragma unroll
        for (int j = 0; j < 8; j++)
            g_O[rbase + j] = acc[i][j] + X[rbase + j];
    }
}

// ---------------------------------------------------------------------------
// K5: LayerNorm rows (gamma=1, beta=0, eps=1e-3) -> d_out. grid = 32768
// ---------------------------------------------------------------------------
__global__ __launch_bounds__(256)
void ln_kernel(float* __restrict__ out)
{
    const size_t base = (size_t)blockIdx.x * DIMC;
    const int t = threadIdx.x;
    float v0 = g_O[base + t];
    float v1 = g_O[base + t + 256];
    float mean = block_sum(v0 + v1) * (1.0f / 512.0f);
    float d0 = v0 - mean, d1 = v1 - mean;
    float var = block_sum(d0 * d0 + d1 * d1) * (1.0f / 512.0f);
    float inv = rsqrtf(var + 1e-3f);
    out[base + t]       = d0 * inv;
    out[base + t + 256] = d1 * inv;
}

// ---------------------------------------------------------------------------
extern "C" void kernel_launch(void* const* d_in, const int* in_sizes, int n_in,
                              void* d_out, int out_size)
{
    const float* X    = (const float*)d_in[0];
    const float* mask = (const float*)d_in[1];
    const float* w1   = (const float*)d_in[2];
    const float* w2   = (const float*)d_in[3];
    const float* w3   = (const float*)d_in[4];
    const float* b1   = (const float*)d_in[5];
    const float* b2   = (const float*)d_in[6];
    const float* b3   = (const float*)d_in[7];
    float* out        = (float*)d_out;

    qkv_kernel<<<dim3(4, 256, 3), 256>>>(X, w1, w2, w3, b1, b2, b3);
    score_kernel<<<dim3(4, 4, 64), 256>>>(mask);
    softmax_kernel<<<32768, 256>>>();
    out_kernel<<<dim3(4, 4, 64), 256>>>(X);
    ln_kernel<<<32768, 256>>>(out);
}

// round 12
// speedup vs baseline: 2.5271x; 2.5271x over previous
#include <cuda_runtime.h>
#include <cuda_bf16.h>
#include <cstdint>

// ---------------------------------------------------------------------------
// Problem constants
// ---------------------------------------------------------------------------
constexpr int DIMC = 512;              // head dim == block_len
constexpr int ROWS = 4 * 16 * 512;     // 32768 total rows
constexpr int BLK_ELEMS = DIMC * DIMC; // per attention block

// Scratch (device globals: allocation-free per harness rules)
__device__ float g_Q[(size_t)ROWS * DIMC];
__device__ float g_K[(size_t)ROWS * DIMC];
__device__ float g_V[(size_t)ROWS * DIMC];
__device__ float g_S[(size_t)ROWS * DIMC];  // scores then probabilities
__device__ float g_O[(size_t)ROWS * DIMC];  // attention out + residual

// ---------------------------------------------------------------------------
// tf32 helpers (base-target safe: mma.sync sm_80+, cvt.rna.tf32 sm_80+)
// ---------------------------------------------------------------------------
__device__ __forceinline__ uint32_t f2tf(float f) {
    uint32_t u;
    asm("cvt.rna.tf32.f32 %0, %1;" : "=r"(u) : "f"(f));
    return u;
}

__device__ __forceinline__ void mma8(float (&c)[4],
                                     uint32_t a0, uint32_t a1, uint32_t a2, uint32_t a3,
                                     uint32_t b0, uint32_t b1) {
    asm volatile(
        "mma.sync.aligned.m16n8k8.row.col.f32.tf32.tf32.f32 "
        "{%0,%1,%2,%3}, {%4,%5,%6,%7}, {%8,%9}, {%0,%1,%2,%3};"
        : "+f"(c[0]), "+f"(c[1]), "+f"(c[2]), "+f"(c[3])
        : "r"(a0), "r"(a1), "r"(a2), "r"(a3), "r"(b0), "r"(b1));
}

// ---------------------------------------------------------------------------
// SMEM layout (dynamic): two double-buffered chunk regions.
//   As[2]: 128 rows x 36 floats (K-chunk 32 + 4 pad)  -> conflict-free frags
//   Bs[2]: BT0: 128 x 36 (K-major);  BT1: 32 x 136 (row-major, pad 8)
// Region size per buffer: 4608 floats. Total = 4 * 4608 * 4B = 73728 B.
// ---------------------------------------------------------------------------
constexpr int REG_F = 4608;
constexpr uint32_t SMEM_BYTES = 4 * REG_F * sizeof(float);

// ---------------------------------------------------------------------------
// 128x128x512 tf32 mma.sync GEMM tile.
// A: [128 x 512] row-major (lda=512), pre-offset to row0.
// BT=0: B K-major [128 n-rows x 512 k] (pre-offset to n0*512): C=A*B^T
// BT=1: B row-major [512 k x 512 n] (pre-offset to col n0):    C=A*B
// 8 warps (2 m x 4 n), warp tile 64x32, acc[mt4][nt4][4].
// ---------------------------------------------------------------------------
template<int BT>
__device__ __forceinline__ void gemm_tile_mma(const float* __restrict__ A,
                                              const float* __restrict__ B,
                                              float (&acc)[4][4][4])
{
    extern __shared__ float sm[];
    float* AsB[2] = { sm,             sm + REG_F     };
    float* BsB[2] = { sm + 2 * REG_F, sm + 3 * REG_F };

    const int tid  = threadIdx.x;
    const int lane = tid & 31, wid = tid >> 5;
    const int wr = wid >> 2, wc = wid & 3;
    const int l4 = lane >> 2, l3 = lane & 3;

    // staging coordinates
    const int ar  = tid >> 1;            // A row 0..127
    const int akh = (tid & 1) * 16;      // A k-half
    const int bk  = tid >> 5;            // BT1: base k row (0..7, +8 per pass)
    const int bn4 = (tid & 31) * 4;      // BT1: n offset

    float4 pa[4], pb[4];

    auto load_chunk = [&](int c) {
        const float* ga = A + (size_t)ar * DIMC + c * 32 + akh;
        #pragma unroll
        for (int i = 0; i < 4; ++i)
            pa[i] = *reinterpret_cast<const float4*>(ga + 4 * i);
        if (BT == 0) {
            const float* gb = B + (size_t)ar * DIMC + c * 32 + akh;
            #pragma unroll
            for (int i = 0; i < 4; ++i)
                pb[i] = *reinterpret_cast<const float4*>(gb + 4 * i);
        } else {
            #pragma unroll
            for (int p = 0; p < 4; ++p)
                pb[p] = *reinterpret_cast<const float4*>(
                    B + (size_t)(c * 32 + bk + p * 8) * DIMC + bn4);
        }
    };

    auto store_chunk = [&](int buf) {
        uint32_t* As = reinterpret_cast<uint32_t*>(AsB[buf]);
        uint32_t* Bs = reinterpret_cast<uint32_t*>(BsB[buf]);
        #pragma unroll
        for (int i = 0; i < 4; ++i) {
            uint4 v = { f2tf(pa[i].x), f2tf(pa[i].y), f2tf(pa[i].z), f2tf(pa[i].w) };
            *reinterpret_cast<uint4*>(As + ar * 36 + akh + 4 * i) = v;
        }
        if (BT == 0) {
            #pragma unroll
            for (int i = 0; i < 4; ++i) {
                uint4 v = { f2tf(pb[i].x), f2tf(pb[i].y), f2tf(pb[i].z), f2tf(pb[i].w) };
                *reinterpret_cast<uint4*>(Bs + ar * 36 + akh + 4 * i) = v;
            }
        } else {
            #pragma unroll
            for (int p = 0; p < 4; ++p) {
                uint4 v = { f2tf(pb[p].x), f2tf(pb[p].y), f2tf(pb[p].z), f2tf(pb[p].w) };
                *reinterpret_cast<uint4*>(Bs + (bk + p * 8) * 136 + bn4) = v;
            }
        }
    };

    load_chunk(0);
    store_chunk(0);
    __syncthreads();

    for (int c = 0; c < 16; ++c) {
        const int buf = c & 1;
        if (c < 15) load_chunk(c + 1);   // prefetch into regs (latency hidden by compute)

        const uint32_t* As = reinterpret_cast<const uint32_t*>(AsB[buf]);
        const uint32_t* Bs = reinterpret_cast<const uint32_t*>(BsB[buf]);

        #pragma unroll
        for (int ks = 0; ks < 4; ++ks) {
            const int k0 = ks * 8;
            uint32_t bf[4][2];
            #pragma unroll
            for (int nt = 0; nt < 4; ++nt) {
                const int N = wc * 32 + nt * 8;
                if (BT == 0) {
                    const uint32_t* p = Bs + (N + l4) * 36 + k0 + l3;
                    bf[nt][0] = p[0];
                    bf[nt][1] = p[4];
                } else {
                    bf[nt][0] = Bs[(k0 + l3) * 136 + N + l4];
                    bf[nt][1] = Bs[(k0 + 4 + l3) * 136 + N + l4];
                }
            }
            #pragma unroll
            for (int mt = 0; mt < 4; ++mt) {
                const int R = wr * 64 + mt * 16;
                const uint32_t a0 = As[(R + l4) * 36 + k0 + l3];
                const uint32_t a1 = As[(R + 8 + l4) * 36 + k0 + l3];
                const uint32_t a2 = As[(R + l4) * 36 + k0 + 4 + l3];
                const uint32_t a3 = As[(R + 8 + l4) * 36 + k0 + 4 + l3];
                #pragma unroll
                for (int nt = 0; nt < 4; ++nt)
                    mma8(acc[mt][nt], a0, a1, a2, a3, bf[nt][0], bf[nt][1]);
            }
        }

        if (c < 15) store_chunk(buf ^ 1);  // prior readers of that buffer synced last iter
        __syncthreads();
    }
}

// Epilogue index helper: fragment (mt,nt) covers rows {r, r+8}, cols {c, c+1}.
#define EPI_COORDS() \
    const int lane = threadIdx.x & 31, wid = threadIdx.x >> 5; \
    const int wr = wid >> 2, wc = wid & 3; \
    const int l4 = lane >> 2, l3 = lane & 3;

// ---------------------------------------------------------------------------
// K1: Q/K/V = X @ W{1,2,3} + b.  grid = (4, 256, 3), block = 256
// ---------------------------------------------------------------------------
__global__ __launch_bounds__(256)
void qkv_kernel(const float* __restrict__ X,
                const float* __restrict__ W1, const float* __restrict__ W2, const float* __restrict__ W3,
                const float* __restrict__ B1, const float* __restrict__ B2, const float* __restrict__ B3)
{
    const float* W    = (blockIdx.z == 0) ? W1 : (blockIdx.z == 1) ? W2 : W3;
    const float* bias = (blockIdx.z == 0) ? B1 : (blockIdx.z == 1) ? B2 : B3;
    float*       C    = (blockIdx.z == 0) ? g_Q : (blockIdx.z == 1) ? g_K : g_V;

    const int row0 = blockIdx.y * 128;
    const int col0 = blockIdx.x * 128;

    float acc[4][4][4] = {};
    gemm_tile_mma<1>(X + (size_t)row0 * DIMC, W + col0, acc);

    EPI_COORDS();
    #pragma unroll
    for (int mt = 0; mt < 4; ++mt) {
        const int row = row0 + wr * 64 + mt * 16 + l4;
        #pragma unroll
        for (int nt = 0; nt < 4; ++nt) {
            const int col = col0 + wc * 32 + nt * 8 + 2 * l3;
            float2 bv = *reinterpret_cast<const float2*>(bias + col);
            float2 v0 = { acc[mt][nt][0] + bv.x, acc[mt][nt][1] + bv.y };
            float2 v1 = { acc[mt][nt][2] + bv.x, acc[mt][nt][3] + bv.y };
            *reinterpret_cast<float2*>(C + (size_t)row * DIMC + col)       = v0;
            *reinterpret_cast<float2*>(C + (size_t)(row + 8) * DIMC + col) = v1;
        }
    }
}

// ---------------------------------------------------------------------------
// K2: S = (Q @ K^T)*scale + (1-mask)*(-1e10).  grid = (4, 4, 64)
// ---------------------------------------------------------------------------
__global__ __launch_bounds__(256)
void score_kernel(const float* __restrict__ mask)
{
    const int bn = blockIdx.z;
    const int q0 = blockIdx.y * 128;
    const int k0 = blockIdx.x * 128;

    float acc[4][4][4] = {};
    gemm_tile_mma<0>(g_Q + (size_t)bn * BLK_ELEMS + (size_t)q0 * DIMC,
                     g_K + (size_t)bn * BLK_ELEMS + (size_t)k0 * DIMC, acc);

    const float scale = 0.04419417382415922f;  // 1/sqrt(512)
    EPI_COORDS();
    #pragma unroll
    for (int mt = 0; mt < 4; ++mt) {
        const int row = bn * DIMC + q0 + wr * 64 + mt * 16 + l4;
        #pragma unroll
        for (int nt = 0; nt < 4; ++nt) {
            const int col = k0 + wc * 32 + nt * 8 + 2 * l3;
            const size_t a0 = (size_t)row * DIMC + col;
            const size_t a1 = (size_t)(row + 8) * DIMC + col;
            float2 m0 = *reinterpret_cast<const float2*>(mask + a0);
            float2 m1 = *reinterpret_cast<const float2*>(mask + a1);
            float2 v0 = { acc[mt][nt][0] * scale + (1.0f - m0.x) * (-1e10f),
                          acc[mt][nt][1] * scale + (1.0f - m0.y) * (-1e10f) };
            float2 v1 = { acc[mt][nt][2] * scale + (1.0f - m1.x) * (-1e10f),
                          acc[mt][nt][3] * scale + (1.0f - m1.y) * (-1e10f) };
            *reinterpret_cast<float2*>(g_S + a0) = v0;
            *reinterpret_cast<float2*>(g_S + a1) = v1;
        }
    }
}

// ---------------------------------------------------------------------------
// K4: O = P @ V + X (residual).  grid = (4, 4, 64)
// ---------------------------------------------------------------------------
__global__ __launch_bounds__(256)
void out_kernel(const float* __restrict__ X)
{
    const int bn = blockIdx.z;
    const int m0 = blockIdx.y * 128;
    const int n0 = blockIdx.x * 128;

    float acc[4][4][4] = {};
    gemm_tile_mma<1>(g_S + (size_t)bn * BLK_ELEMS + (size_t)m0 * DIMC,
                     g_V + (size_t)bn * BLK_ELEMS + n0, acc);

    EPI_COORDS();
    #pragma unroll
    for (int mt = 0; mt < 4; ++mt) {
        const int row = bn * DIMC + m0 + wr * 64 + mt * 16 + l4;
        #pragma unroll
        for (int nt = 0; nt < 4; ++nt) {
            const int col = n0 + wc * 32 + nt * 8 + 2 * l3;
            const size_t a0 = (size_t)row * DIMC + col;
            const size_t a1 = (size_t)(row + 8) * DIMC + col;
            float2 x0 = *reinterpret_cast<const float2*>(X + a0);
            float2 x1 = *reinterpret_cast<const float2*>(X + a1);
            float2 v0 = { acc[mt][nt][0] + x0.x, acc[mt][nt][1] + x0.y };
            float2 v1 = { acc[mt][nt][2] + x1.x, acc[mt][nt][3] + x1.y };
            *reinterpret_cast<float2*>(g_O + a0) = v0;
            *reinterpret_cast<float2*>(g_O + a1) = v1;
        }
    }
}

// ---------------------------------------------------------------------------
// Block reductions (256 threads = 8 warps)
// ---------------------------------------------------------------------------
__device__ __forceinline__ float block_sum(float v)
{
    __shared__ float sb[8];
    const int lane = threadIdx.x & 31, w = threadIdx.x >> 5;
    #pragma unroll
    for (int o = 16; o; o >>= 1) v += __shfl_xor_sync(0xffffffffu, v, o);
    if (lane == 0) sb[w] = v;
    __syncthreads();
    if (w == 0) {
        float r = (lane < 8) ? sb[lane] : 0.0f;
        #pragma unroll
        for (int o = 4; o; o >>= 1) r += __shfl_xor_sync(0xffffffffu, r, o);
        if (lane == 0) sb[0] = r;
    }
    __syncthreads();
    float r = sb[0];
    __syncthreads();
    return r;
}

__device__ __forceinline__ float block_max(float v)
{
    __shared__ float sm2[8];
    const int lane = threadIdx.x & 31, w = threadIdx.x >> 5;
    #pragma unroll
    for (int o = 16; o; o >>= 1) v = fmaxf(v, __shfl_xor_sync(0xffffffffu, v, o));
    if (lane == 0) sm2[w] = v;
    __syncthreads();
    if (w == 0) {
        float r = (lane < 8) ? sm2[lane] : -3.4e38f;
        #pragma unroll
        for (int o = 4; o; o >>= 1) r = fmaxf(r, __shfl_xor_sync(0xffffffffu, r, o));
        if (lane == 0) sm2[0] = r;
    }
    __syncthreads();
    float r = sm2[0];
    __syncthreads();
    return r;
}

// ---------------------------------------------------------------------------
// K3: row softmax over g_S, in place. grid = 32768, block = 256
// ---------------------------------------------------------------------------
__global__ __launch_bounds__(256)
void softmax_kernel()
{
    const size_t base = (size_t)blockIdx.x * DIMC;
    const int t = threadIdx.x;
    float v0 = g_S[base + t];
    float v1 = g_S[base + t + 256];
    float mx = block_max(fmaxf(v0, v1));
    float e0 = __expf(v0 - mx);
    float e1 = __expf(v1 - mx);
    float inv = 1.0f / block_sum(e0 + e1);
    g_S[base + t]       = e0 * inv;
    g_S[base + t + 256] = e1 * inv;
}

// ---------------------------------------------------------------------------
// K5: LayerNorm rows (eps=1e-3) -> d_out. grid = 32768
// ---------------------------------------------------------------------------
__global__ __launch_bounds__(256)
void ln_kernel(float* __restrict__ out)
{
    const size_t base = (size_t)blockIdx.x * DIMC;
    const int t = threadIdx.x;
    float v0 = g_O[base + t];
    float v1 = g_O[base + t + 256];
    float mean = block_sum(v0 + v1) * (1.0f / 512.0f);
    float d0 = v0 - mean, d1 = v1 - mean;
    float var = block_sum(d0 * d0 + d1 * d1) * (1.0f / 512.0f);
    float inv = rsqrtf(var + 1e-3f);
    out[base + t]       = d0 * inv;
    out[base + t + 256] = d1 * inv;
}

// ---------------------------------------------------------------------------
extern "C" void kernel_launch(void* const* d_in, const int* in_sizes, int n_in,
                              void* d_out, int out_size)
{
    const float* X    = (const float*)d_in[0];
    const float* mask = (const float*)d_in[1];
    const float* w1   = (const float*)d_in[2];
    const float* w2   = (const float*)d_in[3];
    const float* w3   = (const float*)d_in[4];
    const float* b1   = (const float*)d_in[5];
    const float* b2   = (const float*)d_in[6];
    const float* b3   = (const float*)d_in[7];
    float* out        = (float*)d_out;

    // Unconditional, idempotent (no static guards per harness rules).
    cudaFuncSetAttribute(qkv_kernel,   cudaFuncAttributeMaxDynamicSharedMemorySize, SMEM_BYTES);
    cudaFuncSetAttribute(score_kernel, cudaFuncAttributeMaxDynamicSharedMemorySize, SMEM_BYTES);
    cudaFuncSetAttribute(out_kernel,   cudaFuncAttributeMaxDynamicSharedMemorySize, SMEM_BYTES);

    qkv_kernel<<<dim3(4, 256, 3), 256, SMEM_BYTES>>>(X, w1, w2, w3, b1, b2, b3);
    score_kernel<<<dim3(4, 4, 64), 256, SMEM_BYTES>>>(mask);
    softmax_kernel<<<32768, 256>>>();
    out_kernel<<<dim3(4, 4, 64), 256, SMEM_BYTES>>>(X);
    ln_kernel<<<32768, 256>>>(out);
}

// round 13
// speedup vs baseline: 3.4249x; 1.3553x over previous
#include <cuda_runtime.h>
#include <cuda_bf16.h>
#include <cstdint>

// ---------------------------------------------------------------------------
// Problem constants
// ---------------------------------------------------------------------------
constexpr int DIMC = 512;              // head dim == block_len
constexpr int ROWS = 4 * 16 * 512;     // 32768 total rows
constexpr int BLK_ELEMS = DIMC * DIMC; // per attention block

// Scratch (device globals: allocation-free per harness rules)
__device__ float g_X[(size_t)ROWS * DIMC];   // tf32-rounded copy of inputs
__device__ float g_W[3][(size_t)DIMC * DIMC];// tf32-rounded weights
__device__ float g_Q[(size_t)ROWS * DIMC];   // tf32-rounded
__device__ float g_K[(size_t)ROWS * DIMC];   // tf32-rounded
__device__ float g_V[(size_t)ROWS * DIMC];   // tf32-rounded
__device__ float g_S[(size_t)ROWS * DIMC];   // scores (raw) then probs (tf32-rounded)
__device__ float g_O[(size_t)ROWS * DIMC];   // attention out + residual (raw)

// ---------------------------------------------------------------------------
// Helpers (base-target safe: mma.sync sm_80+, cvt.rna.tf32 sm_80+, cp.async sm_80+)
// ---------------------------------------------------------------------------
__device__ __forceinline__ uint32_t smem_u32(const void* p) {
    uint32_t a;
    asm("{ .reg .u64 t; cvta.to.shared.u64 t, %1; cvt.u32.u64 %0, t; }" : "=r"(a) : "l"(p));
    return a;
}

__device__ __forceinline__ uint32_t f2tf(float f) {
    uint32_t u;
    asm("cvt.rna.tf32.f32 %0, %1;" : "=r"(u) : "f"(f));
    return u;
}
__device__ __forceinline__ float rnd_tf32(float f) { return __uint_as_float(f2tf(f)); }

__device__ __forceinline__ void mma8(float (&c)[4],
                                     uint32_t a0, uint32_t a1, uint32_t a2, uint32_t a3,
                                     uint32_t b0, uint32_t b1) {
    asm volatile(
        "mma.sync.aligned.m16n8k8.row.col.f32.tf32.tf32.f32 "
        "{%0,%1,%2,%3}, {%4,%5,%6,%7}, {%8,%9}, {%0,%1,%2,%3};"
        : "+f"(c[0]), "+f"(c[1]), "+f"(c[2]), "+f"(c[3])
        : "r"(a0), "r"(a1), "r"(a2), "r"(a3), "r"(b0), "r"(b1));
}

__device__ __forceinline__ void cp16(uint32_t dst, const float* src) {
    asm volatile("cp.async.cg.shared.global [%0], [%1], 16;" :: "r"(dst), "l"(src));
}
#define CP_COMMIT() asm volatile("cp.async.commit_group;" ::: "memory")
#define CP_WAIT2()  asm volatile("cp.async.wait_group 2;" ::: "memory")

// ---------------------------------------------------------------------------
// SMEM: 3-stage pipeline. Per stage: A 128x36 floats, B 128x36 (BT0) or
// 32x136 (BT1, fits in 4608). Stage region = 4608 floats.
// Total = 6 * 4608 * 4B = 110592 B  -> 2 CTAs/SM (221 KB <= 228 KB).
// ---------------------------------------------------------------------------
constexpr int STG_F = 4608;
constexpr uint32_t SMEM_BYTES = 6 * STG_F * sizeof(float);

// ---------------------------------------------------------------------------
// 128x128x512 tf32 mma.sync GEMM tile, cp.async 3-stage pipeline.
// All operands must already be tf32-rounded in global memory.
// A: [128 x 512] row-major (pre-offset to row0).
// BT=0: B K-major [128 n-rows x 512 k] (pre-offset n0*512): C = A*B^T
// BT=1: B row-major [512 k x 512 n] (pre-offset to col n0):  C = A*B
// 8 warps (2 m x 4 n), warp tile 64x32, acc[mt4][nt4][4].
// ---------------------------------------------------------------------------
template<int BT>
__device__ __forceinline__ void gemm_cp(const float* __restrict__ A,
                                        const float* __restrict__ B,
                                        float (&acc)[4][4][4])
{
    extern __shared__ float smf[];
    const uint32_t sbase = smem_u32(smf);
    const int tid  = threadIdx.x;
    const int lane = tid & 31, wid = tid >> 5;
    const int wr = wid >> 2, wc = wid & 3;
    const int l4 = lane >> 2, l3 = lane & 3;

    auto issue_stage = [&](int s, int c) {
        // A: 128 rows x 8 segs(16B); 1024 segs, 4 per thread
        #pragma unroll
        for (int i = 0; i < 4; ++i) {
            const int seg = tid + i * 256;
            const int row = seg >> 3, col = (seg & 7) * 4;
            cp16(sbase + (uint32_t)(s * STG_F + row * 36 + col) * 4,
                 A + (size_t)row * DIMC + c * 32 + col);
        }
        if (BT == 0) {
            #pragma unroll
            for (int i = 0; i < 4; ++i) {
                const int seg = tid + i * 256;
                const int row = seg >> 3, col = (seg & 7) * 4;
                cp16(sbase + (uint32_t)(3 * STG_F + s * STG_F + row * 36 + col) * 4,
                     B + (size_t)row * DIMC + c * 32 + col);
            }
        } else {
            // B: 32 k-rows x 32 segs(16B) of 128 n-cols
            #pragma unroll
            for (int i = 0; i < 4; ++i) {
                const int seg = tid + i * 256;
                const int k = seg >> 5, col = (seg & 31) * 4;
                cp16(sbase + (uint32_t)(3 * STG_F + s * STG_F + k * 136 + col) * 4,
                     B + (size_t)(c * 32 + k) * DIMC + col);
            }
        }
    };

    issue_stage(0, 0); CP_COMMIT();
    issue_stage(1, 1); CP_COMMIT();
    issue_stage(2, 2); CP_COMMIT();

    int s = 0;  // stage for current chunk
    for (int c = 0; c < 16; ++c) {
        CP_WAIT2();
        __syncthreads();

        const uint32_t* As = reinterpret_cast<const uint32_t*>(smf + s * STG_F);
        const uint32_t* Bs = reinterpret_cast<const uint32_t*>(smf + 3 * STG_F + s * STG_F);

        #pragma unroll
        for (int ks = 0; ks < 4; ++ks) {
            const int k0 = ks * 8;
            uint32_t bf[4][2];
            #pragma unroll
            for (int nt = 0; nt < 4; ++nt) {
                const int N = wc * 32 + nt * 8;
                if (BT == 0) {
                    const uint32_t* p = Bs + (N + l4) * 36 + k0 + l3;
                    bf[nt][0] = p[0];
                    bf[nt][1] = p[4];
                } else {
                    bf[nt][0] = Bs[(k0 + l3) * 136 + N + l4];
                    bf[nt][1] = Bs[(k0 + 4 + l3) * 136 + N + l4];
                }
            }
            #pragma unroll
            for (int mt = 0; mt < 4; ++mt) {
                const int R = wr * 64 + mt * 16;
                const uint32_t a0 = As[(R + l4) * 36 + k0 + l3];
                const uint32_t a1 = As[(R + 8 + l4) * 36 + k0 + l3];
                const uint32_t a2 = As[(R + l4) * 36 + k0 + 4 + l3];
                const uint32_t a3 = As[(R + 8 + l4) * 36 + k0 + 4 + l3];
                #pragma unroll
                for (int nt = 0; nt < 4; ++nt)
                    mma8(acc[mt][nt], a0, a1, a2, a3, bf[nt][0], bf[nt][1]);
            }
        }

        __syncthreads();                    // all warps done reading stage s
        if (c + 3 < 16) issue_stage(s, c + 3);
        CP_COMMIT();                        // empty at tail keeps group count stable
        s = (s == 2) ? 0 : s + 1;
    }
}

// Epilogue index helper: fragment (mt,nt) covers rows {r, r+8}, cols {c, c+1}.
#define EPI_COORDS() \
    const int lane = threadIdx.x & 31, wid = threadIdx.x >> 5; \
    const int wr = wid >> 2, wc = wid & 3; \
    const int l4 = lane >> 2, l3 = lane & 3;

// ---------------------------------------------------------------------------
// K0: tf32-round X and W into g_X / g_W. float4 grid-stride.
// ---------------------------------------------------------------------------
__global__ __launch_bounds__(256)
void cvt_kernel(const float* __restrict__ X,
                const float* __restrict__ W1, const float* __restrict__ W2,
                const float* __restrict__ W3)
{
    const int NX = ROWS * DIMC / 4;          // 4194304 float4
    const int NW = DIMC * DIMC / 4;          // 65536 float4 each
    const int i = blockIdx.x * blockDim.x + threadIdx.x;
    if (i < NX) {
        float4 v = reinterpret_cast<const float4*>(X)[i];
        v.x = rnd_tf32(v.x); v.y = rnd_tf32(v.y); v.z = rnd_tf32(v.z); v.w = rnd_tf32(v.w);
        reinterpret_cast<float4*>(g_X)[i] = v;
    } else {
        const int j = i - NX;
        if (j < 3 * NW) {
            const int w = j / NW, r = j - w * NW;
            const float* W = (w == 0) ? W1 : (w == 1) ? W2 : W3;
            float4 v = reinterpret_cast<const float4*>(W)[r];
            v.x = rnd_tf32(v.x); v.y = rnd_tf32(v.y); v.z = rnd_tf32(v.z); v.w = rnd_tf32(v.w);
            reinterpret_cast<float4*>(g_W[w])[r] = v;
        }
    }
}

// ---------------------------------------------------------------------------
// K1: Q/K/V = X @ W{1,2,3} + b (outputs tf32-rounded). grid=(4,256,3), 256 thr
// ---------------------------------------------------------------------------
__global__ __launch_bounds__(256, 2)
void qkv_kernel(const float* __restrict__ B1, const float* __restrict__ B2,
                const float* __restrict__ B3)
{
    const float* W    = g_W[blockIdx.z];
    const float* bias = (blockIdx.z == 0) ? B1 : (blockIdx.z == 1) ? B2 : B3;
    float*       C    = (blockIdx.z == 0) ? g_Q : (blockIdx.z == 1) ? g_K : g_V;

    const int row0 = blockIdx.y * 128;
    const int col0 = blockIdx.x * 128;

    float acc[4][4][4] = {};
    gemm_cp<1>(g_X + (size_t)row0 * DIMC, W + col0, acc);

    EPI_COORDS();
    #pragma unroll
    for (int mt = 0; mt < 4; ++mt) {
        const int row = row0 + wr * 64 + mt * 16 + l4;
        #pragma unroll
        for (int nt = 0; nt < 4; ++nt) {
            const int col = col0 + wc * 32 + nt * 8 + 2 * l3;
            float2 bv = *reinterpret_cast<const float2*>(bias + col);
            float2 v0 = { rnd_tf32(acc[mt][nt][0] + bv.x), rnd_tf32(acc[mt][nt][1] + bv.y) };
            float2 v1 = { rnd_tf32(acc[mt][nt][2] + bv.x), rnd_tf32(acc[mt][nt][3] + bv.y) };
            *reinterpret_cast<float2*>(C + (size_t)row * DIMC + col)       = v0;
            *reinterpret_cast<float2*>(C + (size_t)(row + 8) * DIMC + col) = v1;
        }
    }
}

// ---------------------------------------------------------------------------
// K2: S = (Q @ K^T)*scale + (1-mask)*(-1e10) (raw fp32). grid=(4,4,64)
// ---------------------------------------------------------------------------
__global__ __launch_bounds__(256, 2)
void score_kernel(const float* __restrict__ mask)
{
    const int bn = blockIdx.z;
    const int q0 = blockIdx.y * 128;
    const int k0 = blockIdx.x * 128;

    float acc[4][4][4] = {};
    gemm_cp<0>(g_Q + (size_t)bn * BLK_ELEMS + (size_t)q0 * DIMC,
               g_K + (size_t)bn * BLK_ELEMS + (size_t)k0 * DIMC, acc);

    const float scale = 0.04419417382415922f;  // 1/sqrt(512)
    EPI_COORDS();
    #pragma unroll
    for (int mt = 0; mt < 4; ++mt) {
        const int row = bn * DIMC + q0 + wr * 64 + mt * 16 + l4;
        #pragma unroll
        for (int nt = 0; nt < 4; ++nt) {
            const int col = k0 + wc * 32 + nt * 8 + 2 * l3;
            const size_t a0 = (size_t)row * DIMC + col;
            const size_t a1 = (size_t)(row + 8) * DIMC + col;
            float2 m0 = *reinterpret_cast<const float2*>(mask + a0);
            float2 m1 = *reinterpret_cast<const float2*>(mask + a1);
            float2 v0 = { acc[mt][nt][0] * scale + (1.0f - m0.x) * (-1e10f),
                          acc[mt][nt][1] * scale + (1.0f - m0.y) * (-1e10f) };
            float2 v1 = { acc[mt][nt][2] * scale + (1.0f - m1.x) * (-1e10f),
                          acc[mt][nt][3] * scale + (1.0f - m1.y) * (-1e10f) };
            *reinterpret_cast<float2*>(g_S + a0) = v0;
            *reinterpret_cast<float2*>(g_S + a1) = v1;
        }
    }
}

// ---------------------------------------------------------------------------
// K4: O = P @ V + X (residual, raw fp32). grid=(4,4,64)
// ---------------------------------------------------------------------------
__global__ __launch_bounds__(256, 2)
void out_kernel(const float* __restrict__ X)
{
    const int bn = blockIdx.z;
    const int m0 = blockIdx.y * 128;
    const int n0 = blockIdx.x * 128;

    float acc[4][4][4] = {};
    gemm_cp<1>(g_S + (size_t)bn * BLK_ELEMS + (size_t)m0 * DIMC,
               g_V + (size_t)bn * BLK_ELEMS + n0, acc);

    EPI_COORDS();
    #pragma unroll
    for (int mt = 0; mt < 4; ++mt) {
        const int row = bn * DIMC + m0 + wr * 64 + mt * 16 + l4;
        #pragma unroll
        for (int nt = 0; nt < 4; ++nt) {
            const int col = n0 + wc * 32 + nt * 8 + 2 * l3;
            const size_t a0 = (size_t)row * DIMC + col;
            const size_t a1 = (size_t)(row + 8) * DIMC + col;
            float2 x0 = *reinterpret_cast<const float2*>(X + a0);
            float2 x1 = *reinterpret_cast<const float2*>(X + a1);
            float2 v0 = { acc[mt][nt][0] + x0.x, acc[mt][nt][1] + x0.y };
            float2 v1 = { acc[mt][nt][2] + x1.x, acc[mt][nt][3] + x1.y };
            *reinterpret_cast<float2*>(g_O + a0) = v0;
            *reinterpret_cast<float2*>(g_O + a1) = v1;
        }
    }
}

// ---------------------------------------------------------------------------
// Block reductions (256 threads = 8 warps)
// ---------------------------------------------------------------------------
__device__ __forceinline__ float block_sum(float v)
{
    __shared__ float sb[8];
    const int lane = threadIdx.x & 31, w = threadIdx.x >> 5;
    #pragma unroll
    for (int o = 16; o; o >>= 1) v += __shfl_xor_sync(0xffffffffu, v, o);
    if (lane == 0) sb[w] = v;
    __syncthreads();
    if (w == 0) {
        float r = (lane < 8) ? sb[lane] : 0.0f;
        #pragma unroll
        for (int o = 4; o; o >>= 1) r += __shfl_xor_sync(0xffffffffu, r, o);
        if (lane == 0) sb[0] = r;
    }
    __syncthreads();
    float r = sb[0];
    __syncthreads();
    return r;
}

__device__ __forceinline__ float block_max(float v)
{
    __shared__ float sm2[8];
    const int lane = threadIdx.x & 31, w = threadIdx.x >> 5;
    #pragma unroll
    for (int o = 16; o; o >>= 1) v = fmaxf(v, __shfl_xor_sync(0xffffffffu, v, o));
    if (lane == 0) sm2[w] = v;
    __syncthreads();
    if (w == 0) {
        float r = (lane < 8) ? sm2[lane] : -3.4e38f;
        #pragma unroll
        for (int o = 4; o; o >>= 1) r = fmaxf(r, __shfl_xor_sync(0xffffffffu, r, o));
        if (lane == 0) sm2[0] = r;
    }
    __syncthreads();
    float r = sm2[0];
    __syncthreads();
    return r;
}

// ---------------------------------------------------------------------------
// K3: row softmax over g_S, in place (probs tf32-rounded). grid=32768
// ---------------------------------------------------------------------------
__global__ __launch_bounds__(256)
void softmax_kernel()
{
    const size_t base = (size_t)blockIdx.x * DIMC;
    const int t = threadIdx.x;
    float v0 = g_S[base + t];
    float v1 = g_S[base + t + 256];
    float mx = block_max(fmaxf(v0, v1));
    float e0 = __expf(v0 - mx);
    float e1 = __expf(v1 - mx);
    float inv = 1.0f / block_sum(e0 + e1);
    g_S[base + t]       = rnd_tf32(e0 * inv);
    g_S[base + t + 256] = rnd_tf32(e1 * inv);
}

// ---------------------------------------------------------------------------
// K5: LayerNorm rows (eps=1e-3) -> d_out. grid=32768
// ---------------------------------------------------------------------------
__global__ __launch_bounds__(256)
void ln_kernel(float* __restrict__ out)
{
    const size_t base = (size_t)blockIdx.x * DIMC;
    const int t = threadIdx.x;
    float v0 = g_O[base + t];
    float v1 = g_O[base + t + 256];
    float mean = block_sum(v0 + v1) * (1.0f / 512.0f);
    float d0 = v0 - mean, d1 = v1 - mean;
    float var = block_sum(d0 * d0 + d1 * d1) * (1.0f / 512.0f);
    float inv = rsqrtf(var + 1e-3f);
    out[base + t]       = d0 * inv;
    out[base + t + 256] = d1 * inv;
}

// ---------------------------------------------------------------------------
extern "C" void kernel_launch(void* const* d_in, const int* in_sizes, int n_in,
                              void* d_out, int out_size)
{
    const float* X    = (const float*)d_in[0];
    const float* mask = (const float*)d_in[1];
    const float* w1   = (const float*)d_in[2];
    const float* w2   = (const float*)d_in[3];
    const float* w3   = (const float*)d_in[4];
    const float* b1   = (const float*)d_in[5];
    const float* b2   = (const float*)d_in[6];
    const float* b3   = (const float*)d_in[7];
    float* out        = (float*)d_out;

    // Unconditional, idempotent (no static guards per harness rules).
    cudaFuncSetAttribute(qkv_kernel,   cudaFuncAttributeMaxDynamicSharedMemorySize, SMEM_BYTES);
    cudaFuncSetAttribute(score_kernel, cudaFuncAttributeMaxDynamicSharedMemorySize, SMEM_BYTES);
    cudaFuncSetAttribute(out_kernel,   cudaFuncAttributeMaxDynamicSharedMemorySize, SMEM_BYTES);

    const int NCVT = ROWS * DIMC / 4 + 3 * DIMC * DIMC / 4;
    cvt_kernel<<<(NCVT + 255) / 256, 256>>>(X, w1, w2, w3);
    qkv_kernel<<<dim3(4, 256, 3), 256, SMEM_BYTES>>>(b1, b2, b3);
    score_kernel<<<dim3(4, 4, 64), 256, SMEM_BYTES>>>(mask);
    softmax_kernel<<<32768, 256>>>();
    out_kernel<<<dim3(4, 4, 64), 256, SMEM_BYTES>>>(X);
    ln_kernel<<<32768, 256>>>(out);
}

// round 15
// speedup vs baseline: 5.0664x; 1.4793x over previous
#include <cuda_runtime.h>
#include <cuda_bf16.h>
#include <cstdint>

// ---------------------------------------------------------------------------
// Problem constants
// ---------------------------------------------------------------------------
constexpr int DIMC = 512;              // head dim == block_len
constexpr int ROWS = 32768;            // 4 * 16 * 512 total rows
constexpr int BLK_ELEMS = DIMC * DIMC; // per attention block

// Scratch (device globals: allocation-free per harness rules)
__device__ __nv_bfloat16 g_X [(size_t)ROWS * DIMC];   // bf16 inputs (row-major)
__device__ __nv_bfloat16 g_Wt[3][(size_t)DIMC * DIMC];// bf16 W^T (n-major)
__device__ __nv_bfloat16 g_Qb[(size_t)ROWS * DIMC];   // bf16 Q (row-major)
__device__ __nv_bfloat16 g_Kb[(size_t)ROWS * DIMC];   // bf16 K (row-major == n-major for QK^T)
__device__ __nv_bfloat16 g_Vt[(size_t)ROWS * DIMC];   // bf16 V^T per block: [64][512 d][512 seq]
__device__ float         g_S [(size_t)ROWS * DIMC];   // raw fp32 scores
__device__ __nv_bfloat16 g_P [(size_t)ROWS * DIMC];   // bf16 probabilities
__device__ float         g_O [(size_t)ROWS * DIMC];   // attention out + residual (fp32)

// ---------------------------------------------------------------------------
// Helpers (base-target safe: mma.sync bf16 sm_80+, cp.async sm_80+)
// ---------------------------------------------------------------------------
__device__ __forceinline__ uint32_t smem_u32(const void* p) {
    uint32_t a;
    asm("{ .reg .u64 t; cvta.to.shared.u64 t, %1; cvt.u32.u64 %0, t; }" : "=r"(a) : "l"(p));
    return a;
}

__device__ __forceinline__ void mma16(float (&c)[4],
                                      uint32_t a0, uint32_t a1, uint32_t a2, uint32_t a3,
                                      uint32_t b0, uint32_t b1) {
    asm volatile(
        "mma.sync.aligned.m16n8k16.row.col.f32.bf16.bf16.f32 "
        "{%0,%1,%2,%3}, {%4,%5,%6,%7}, {%8,%9}, {%0,%1,%2,%3};"
        : "+f"(c[0]), "+f"(c[1]), "+f"(c[2]), "+f"(c[3])
        : "r"(a0), "r"(a1), "r"(a2), "r"(a3), "r"(b0), "r"(b1));
}

__device__ __forceinline__ void cp16(uint32_t dst, const void* src) {
    asm volatile("cp.async.cg.shared.global [%0], [%1], 16;" :: "r"(dst), "l"(src));
}
#define CP_COMMIT() asm volatile("cp.async.commit_group;" ::: "memory")
#define CP_WAIT2()  asm volatile("cp.async.wait_group 2;" ::: "memory")

// ---------------------------------------------------------------------------
// SMEM: 3-stage pipeline, bf16. Per stage per operand: 128 rows x 72 halves
// (64 data + 8 pad) = 9216 halves = 18432 B. Stage (A+B) = 36864 B.
// Total = 3 * 36864 = 110592 B -> 2 CTAs/SM.
// Fragment LDS word = row*36 + kw + l3 -> bank 4*row + l3 : conflict-free.
// ---------------------------------------------------------------------------
constexpr int STG_H = 9216;                       // halves per operand stage
constexpr uint32_t SMEM_BYTES = 6 * STG_H * 2;    // 110592

// ---------------------------------------------------------------------------
// 128x128x512 bf16 mma.sync GEMM: C = A * B^T
// A: [128 x 512] bf16 row-major (pre-offset). B: [128 n x 512 k] bf16 n-major
// (pre-offset). 8 warps (2m x 4n), warp tile 64x32, acc[mt4][nt4][4] fp32.
// K chunked by 64 halves (8 chunks), 4 k16-steps per chunk.
// ---------------------------------------------------------------------------
__device__ __forceinline__ void gemm_bf16(const __nv_bfloat16* __restrict__ A,
                                          const __nv_bfloat16* __restrict__ B,
                                          float (&acc)[4][4][4])
{
    extern __shared__ __align__(16) uint16_t smh[];
    const uint32_t sbase = smem_u32(smh);
    const int tid  = threadIdx.x;
    const int lane = tid & 31, wid = tid >> 5;
    const int wr = wid >> 2, wc = wid & 3;
    const int l4 = lane >> 2, l3 = lane & 3;

    auto issue = [&](int s, int c) {
        #pragma unroll
        for (int i = 0; i < 4; ++i) {
            const int seg = tid + i * 256;          // 1024 segs per operand
            const int row = seg >> 3, sc = (seg & 7) * 8;
            cp16(sbase + (uint32_t)(s * STG_H + row * 72 + sc) * 2,
                 A + (size_t)row * DIMC + c * 64 + sc);
            cp16(sbase + (uint32_t)((3 + s) * STG_H + row * 72 + sc) * 2,
                 B + (size_t)row * DIMC + c * 64 + sc);
        }
    };

    issue(0, 0); CP_COMMIT();
    issue(1, 1); CP_COMMIT();
    issue(2, 2); CP_COMMIT();

    int s = 0;
    for (int c = 0; c < 8; ++c) {
        CP_WAIT2();
        __syncthreads();

        const uint32_t* Aw = reinterpret_cast<const uint32_t*>(smh + s * STG_H);
        const uint32_t* Bw = reinterpret_cast<const uint32_t*>(smh + (3 + s) * STG_H);

        #pragma unroll
        for (int ks = 0; ks < 4; ++ks) {
            const int kw = ks * 8;                  // word offset of k16 step
            uint32_t bf[4][2];
            #pragma unroll
            for (int nt = 0; nt < 4; ++nt) {
                const int base = (wc * 32 + nt * 8 + l4) * 36 + kw + l3;
                bf[nt][0] = Bw[base];
                bf[nt][1] = Bw[base + 4];
            }
            #pragma unroll
            for (int mt = 0; mt < 4; ++mt) {
                const int base = (wr * 64 + mt * 16 + l4) * 36 + kw + l3;
                const uint32_t a0 = Aw[base],     a1 = Aw[base + 288];   // +8 rows
                const uint32_t a2 = Aw[base + 4], a3 = Aw[base + 292];
                #pragma unroll
                for (int nt = 0; nt < 4; ++nt)
                    mma16(acc[mt][nt], a0, a1, a2, a3, bf[nt][0], bf[nt][1]);
            }
        }

        __syncthreads();
        if (c + 3 < 8) issue(s, c + 3);
        CP_COMMIT();                                // empty at tail keeps count
        s = (s == 2) ? 0 : s + 1;
    }
}

// Fragment (mt,nt) covers rows {r, r+8}, col pair {c, c+1}.
#define EPI_COORDS() \
    const int lane = threadIdx.x & 31, wid = threadIdx.x >> 5; \
    const int wr = wid >> 2, wc = wid & 3; \
    const int l4 = lane >> 2, l3 = lane & 3;

// ---------------------------------------------------------------------------
// K0: X -> g_X bf16 ; W{1,2,3} -> g_Wt transposed bf16.
// ---------------------------------------------------------------------------
__global__ __launch_bounds__(256)
void cvt_kernel(const float* __restrict__ X,
                const float* __restrict__ W1, const float* __restrict__ W2,
                const float* __restrict__ W3)
{
    const int NX4 = ROWS * DIMC / 4;
    const int NW4 = DIMC * DIMC / 4;
    const int i = blockIdx.x * blockDim.x + threadIdx.x;
    if (i < NX4) {
        float4 v = reinterpret_cast<const float4*>(X)[i];
        *reinterpret_cast<__nv_bfloat162*>(g_X + (size_t)4 * i)     = __floats2bfloat162_rn(v.x, v.y);
        *reinterpret_cast<__nv_bfloat162*>(g_X + (size_t)4 * i + 2) = __floats2bfloat162_rn(v.z, v.w);
    } else if (i < NX4 + 3 * NW4) {
        int j = i - NX4;
        const int w = j / NW4; j -= w * NW4;
        const int k = j >> 7, n4 = (j & 127) * 4;
        const float* W = (w == 0) ? W1 : (w == 1) ? W2 : W3;
        float4 v = *reinterpret_cast<const float4*>(W + (size_t)k * DIMC + n4);
        g_Wt[w][(size_t)(n4 + 0) * DIMC + k] = __float2bfloat16(v.x);
        g_Wt[w][(size_t)(n4 + 1) * DIMC + k] = __float2bfloat16(v.y);
        g_Wt[w][(size_t)(n4 + 2) * DIMC + k] = __float2bfloat16(v.z);
        g_Wt[w][(size_t)(n4 + 3) * DIMC + k] = __float2bfloat16(v.w);
    }
}

// ---------------------------------------------------------------------------
// K1: Q/K/V = X @ W + b. grid=(4,256,3), 256 thr.
// z<2 -> row-major bf16 Q/K.  z==2 -> V^T via smem transpose (stride 136).
// ---------------------------------------------------------------------------
__global__ __launch_bounds__(256, 2)
void qkv_kernel(const float* __restrict__ B1, const float* __restrict__ B2,
                const float* __restrict__ B3)
{
    const int z = blockIdx.z;
    const int row0 = blockIdx.y * 128;
    const int col0 = blockIdx.x * 128;
    const float* bias = (z == 0) ? B1 : (z == 1) ? B2 : B3;

    float acc[4][4][4] = {};
    gemm_bf16(g_X + (size_t)row0 * DIMC, g_Wt[z] + (size_t)col0 * DIMC, acc);

    EPI_COORDS();
    if (z < 2) {
        __nv_bfloat16* C = (z == 0) ? g_Qb : g_Kb;
        #pragma unroll
        for (int mt = 0; mt < 4; ++mt) {
            const int row = row0 + wr * 64 + mt * 16 + l4;
            #pragma unroll
            for (int nt = 0; nt < 4; ++nt) {
                const int col = col0 + wc * 32 + nt * 8 + 2 * l3;
                float2 bv = *reinterpret_cast<const float2*>(bias + col);
                __nv_bfloat162 v0 = __floats2bfloat162_rn(acc[mt][nt][0] + bv.x, acc[mt][nt][1] + bv.y);
                __nv_bfloat162 v1 = __floats2bfloat162_rn(acc[mt][nt][2] + bv.x, acc[mt][nt][3] + bv.y);
                *reinterpret_cast<__nv_bfloat162*>(C + (size_t)row * DIMC + col)       = v0;
                *reinterpret_cast<__nv_bfloat162*>(C + (size_t)(row + 8) * DIMC + col) = v1;
            }
        }
    } else {
        extern __shared__ __align__(16) uint16_t smh[];
        __syncthreads();   // pipeline smem dead; reuse as 128x136-half tile
        #pragma unroll
        for (int mt = 0; mt < 4; ++mt) {
            const int r = wr * 64 + mt * 16 + l4;
            #pragma unroll
            for (int nt = 0; nt < 4; ++nt) {
                const int cl = wc * 32 + nt * 8 + 2 * l3;
                float2 bv = *reinterpret_cast<const float2*>(bias + col0 + cl);
                __nv_bfloat162 v0 = __floats2bfloat162_rn(acc[mt][nt][0] + bv.x, acc[mt][nt][1] + bv.y);
                __nv_bfloat162 v1 = __floats2bfloat162_rn(acc[mt][nt][2] + bv.x, acc[mt][nt][3] + bv.y);
                *reinterpret_cast<__nv_bfloat162*>(smh + (size_t)r * 136 + cl)       = v0;
                *reinterpret_cast<__nv_bfloat162*>(smh + (size_t)(r + 8) * 136 + cl) = v1;
            }
        }
        __syncthreads();
        const int tid = threadIdx.x;
        const int d = tid & 127, half = tid >> 7;
        const int bn = row0 >> 9, seq0 = row0 & 511;
        __nv_bfloat16* dst = g_Vt + ((size_t)(bn * DIMC + col0 + d)) * DIMC + seq0 + half * 64;
        #pragma unroll
        for (int i = 0; i < 8; ++i) {
            uint16_t tmp[8];
            #pragma unroll
            for (int j = 0; j < 8; ++j)
                tmp[j] = smh[(size_t)(half * 64 + i * 8 + j) * 136 + d];
            *reinterpret_cast<uint4*>(dst + i * 8) = *reinterpret_cast<const uint4*>(tmp);
        }
    }
}

// ---------------------------------------------------------------------------
// K2: S = (Q @ K^T)*scale + (1-mask)*(-1e10) (fp32). grid=(4,4,64)
// ---------------------------------------------------------------------------
__global__ __launch_bounds__(256, 2)
void score_kernel(const float* __restrict__ mask)
{
    const int bn = blockIdx.z;
    const int q0 = blockIdx.y * 128;
    const int k0 = blockIdx.x * 128;

    float acc[4][4][4] = {};
    gemm_bf16(g_Qb + (size_t)bn * BLK_ELEMS + (size_t)q0 * DIMC,
              g_Kb + (size_t)bn * BLK_ELEMS + (size_t)k0 * DIMC, acc);

    const float scale = 0.04419417382415922f;  // 1/sqrt(512)
    EPI_COORDS();
    #pragma unroll
    for (int mt = 0; mt < 4; ++mt) {
        const int row = bn * DIMC + q0 + wr * 64 + mt * 16 + l4;
        #pragma unroll
        for (int nt = 0; nt < 4; ++nt) {
            const int col = k0 + wc * 32 + nt * 8 + 2 * l3;
            const size_t a0 = (size_t)row * DIMC + col;
            const size_t a1 = (size_t)(row + 8) * DIMC + col;
            float2 m0 = *reinterpret_cast<const float2*>(mask + a0);
            float2 m1 = *reinterpret_cast<const float2*>(mask + a1);
            float2 v0 = { acc[mt][nt][0] * scale + (1.0f - m0.x) * (-1e10f),
                          acc[mt][nt][1] * scale + (1.0f - m0.y) * (-1e10f) };
            float2 v1 = { acc[mt][nt][2] * scale + (1.0f - m1.x) * (-1e10f),
                          acc[mt][nt][3] * scale + (1.0f - m1.y) * (-1e10f) };
            *reinterpret_cast<float2*>(g_S + a0) = v0;
            *reinterpret_cast<float2*>(g_S + a1) = v1;
        }
    }
}

// ---------------------------------------------------------------------------
// K4: O = P @ V + X (residual, fp32). grid=(4,4,64). B = V^T (n-major).
// ---------------------------------------------------------------------------
__global__ __launch_bounds__(256, 2)
void out_kernel(const float* __restrict__ X)
{
    const int bn = blockIdx.z;
    const int m0 = blockIdx.y * 128;
    const int n0 = blockIdx.x * 128;

    float acc[4][4][4] = {};
    gemm_bf16(g_P  + (size_t)bn * BLK_ELEMS + (size_t)m0 * DIMC,
              g_Vt + (size_t)bn * BLK_ELEMS + (size_t)n0 * DIMC, acc);

    EPI_COORDS();
    #pragma unroll
    for (int mt = 0; mt < 4; ++mt) {
        const int row = bn * DIMC + m0 + wr * 64 + mt * 16 + l4;
        #pragma unroll
        for (int nt = 0; nt < 4; ++nt) {
            const int col = n0 + wc * 32 + nt * 8 + 2 * l3;
            const size_t a0 = (size_t)row * DIMC + col;
            const size_t a1 = (size_t)(row + 8) * DIMC + col;
            float2 x0 = *reinterpret_cast<const float2*>(X + a0);
            float2 x1 = *reinterpret_cast<const float2*>(X + a1);
            float2 v0 = { acc[mt][nt][0] + x0.x, acc[mt][nt][1] + x0.y };
            float2 v1 = { acc[mt][nt][2] + x1.x, acc[mt][nt][3] + x1.y };
            *reinterpret_cast<float2*>(g_O + a0) = v0;
            *reinterpret_cast<float2*>(g_O + a1) = v1;
        }
    }
}

// ---------------------------------------------------------------------------
// Block reductions (256 threads = 8 warps)
// ---------------------------------------------------------------------------
__device__ __forceinline__ float block_sum(float v)
{
    __shared__ float sb[8];
    const int lane = threadIdx.x & 31, w = threadIdx.x >> 5;
    #pragma unroll
    for (int o = 16; o; o >>= 1) v += __shfl_xor_sync(0xffffffffu, v, o);
    if (lane == 0) sb[w] = v;
    __syncthreads();
    if (w == 0) {
        float r = (lane < 8) ? sb[lane] : 0.0f;
        #pragma unroll
        for (int o = 4; o; o >>= 1) r += __shfl_xor_sync(0xffffffffu, r, o);
        if (lane == 0) sb[0] = r;
    }
    __syncthreads();
    float r = sb[0];
    __syncthreads();
    return r;
}

__device__ __forceinline__ float block_max(float v)
{
    __shared__ float sm2[8];
    const int lane = threadIdx.x & 31, w = threadIdx.x >> 5;
    #pragma unroll
    for (int o = 16; o; o >>= 1) v = fmaxf(v, __shfl_xor_sync(0xffffffffu, v, o));
    if (lane == 0) sm2[w] = v;
    __syncthreads();
    if (w == 0) {
        float r = (lane < 8) ? sm2[lane] : -3.4e38f;
        #pragma unroll
        for (int o = 4; o; o >>= 1) r = fmaxf(r, __shfl_xor_sync(0xffffffffu, r, o));
        if (lane == 0) sm2[0] = r;
    }
    __syncthreads();
    float r = sm2[0];
    __syncthreads();
    return r;
}

// ---------------------------------------------------------------------------
// K3: row softmax over g_S -> g_P bf16. grid=32768
// ---------------------------------------------------------------------------
__global__ __launch_bounds__(256)
void softmax_kernel()
{
    const size_t base = (size_t)blockIdx.x * DIMC;
    const int t = threadIdx.x;
    float v0 = g_S[base + t];
    float v1 = g_S[base + t + 256];
    float mx = block_max(fmaxf(v0, v1));
    float e0 = __expf(v0 - mx);
    float e1 = __expf(v1 - mx);
    float inv = 1.0f / block_sum(e0 + e1);
    g_P[base + t]       = __float2bfloat16(e0 * inv);
    g_P[base + t + 256] = __float2bfloat16(e1 * inv);
}

// ---------------------------------------------------------------------------
// K5: LayerNorm rows (eps=1e-3) -> d_out. grid=32768
// ---------------------------------------------------------------------------
__global__ __launch_bounds__(256)
void ln_kernel(float* __restrict__ out)
{
    const size_t base = (size_t)blockIdx.x * DIMC;
    const int t = threadIdx.x;
    float v0 = g_O[base + t];
    float v1 = g_O[base + t + 256];
    float mean = block_sum(v0 + v1) * (1.0f / 512.0f);
    float d0 = v0 - mean, d1 = v1 - mean;
    float var = block_sum(d0 * d0 + d1 * d1) * (1.0f / 512.0f);
    float inv = rsqrtf(var + 1e-3f);
    out[base + t]       = d0 * inv;
    out[base + t + 256] = d1 * inv;
}

// ---------------------------------------------------------------------------
extern "C" void kernel_launch(void* const* d_in, const int* in_sizes, int n_in,
                              void* d_out, int out_size)
{
    const float* X    = (const float*)d_in[0];
    const float* mask = (const float*)d_in[1];
    const float* w1   = (const float*)d_in[2];
    const float* w2   = (const float*)d_in[3];
    const float* w3   = (const float*)d_in[4];
    const float* b1   = (const float*)d_in[5];
    const float* b2   = (const float*)d_in[6];
    const float* b3   = (const float*)d_in[7];
    float* out        = (float*)d_out;

    // Unconditional, idempotent (no static guards per harness rules).
    cudaFuncSetAttribute(qkv_kernel,   cudaFuncAttributeMaxDynamicSharedMemorySize, SMEM_BYTES);
    cudaFuncSetAttribute(score_kernel, cudaFuncAttributeMaxDynamicSharedMemorySize, SMEM_BYTES);
    cudaFuncSetAttribute(out_kernel,   cudaFuncAttributeMaxDynamicSharedMemorySize, SMEM_BYTES);

    const int NCVT = ROWS * DIMC / 4 + 3 * DIMC * DIMC / 4;
    cvt_kernel<<<(NCVT + 255) / 256, 256>>>(X, w1, w2, w3);
    qkv_kernel<<<dim3(4, 256, 3), 256, SMEM_BYTES>>>(b1, b2, b3);
    score_kernel<<<dim3(4, 4, 64), 256, SMEM_BYTES>>>(mask);
    softmax_kernel<<<32768, 256>>>();
    out_kernel<<<dim3(4, 4, 64), 256, SMEM_BYTES>>>(X);
    ln_kernel<<<32768, 256>>>(out);
}

// round 17
// speedup vs baseline: 5.4844x; 1.0825x over previous
#include <cuda_runtime.h>
#include <cuda_bf16.h>
#include <cstdint>

// ---------------------------------------------------------------------------
// Problem constants
// ---------------------------------------------------------------------------
constexpr int DIMC = 512;              // head dim == block_len
constexpr int ROWS = 32768;            // 4 * 16 * 512 total rows
constexpr int BLK_ELEMS = DIMC * DIMC; // per attention block

// Scratch (device globals: allocation-free per harness rules)
__device__ __nv_bfloat16 g_X [(size_t)ROWS * DIMC];   // bf16 inputs (row-major)
__device__ __nv_bfloat16 g_Wt[3][(size_t)DIMC * DIMC];// bf16 W^T (n-major)
__device__ __nv_bfloat16 g_Qb[(size_t)ROWS * DIMC];   // bf16 Q (row-major)
__device__ __nv_bfloat16 g_Kb[(size_t)ROWS * DIMC];   // bf16 K (row-major == n-major)
__device__ __nv_bfloat16 g_Vt[(size_t)ROWS * DIMC];   // bf16 V^T per block: [64][512 d][512 seq]
__device__ __nv_bfloat16 g_P [(size_t)ROWS * DIMC];   // bf16 probabilities

// ---------------------------------------------------------------------------
// Helpers (base-target safe: bf16 mma.sync sm_80+, cp.async sm_80+)
// ---------------------------------------------------------------------------
__device__ __forceinline__ uint32_t smem_u32(const void* p) {
    uint32_t a;
    asm("{ .reg .u64 t; cvta.to.shared.u64 t, %1; cvt.u32.u64 %0, t; }" : "=r"(a) : "l"(p));
    return a;
}

__device__ __forceinline__ void mma16(float (&c)[4],
                                      uint32_t a0, uint32_t a1, uint32_t a2, uint32_t a3,
                                      uint32_t b0, uint32_t b1) {
    asm volatile(
        "mma.sync.aligned.m16n8k16.row.col.f32.bf16.bf16.f32 "
        "{%0,%1,%2,%3}, {%4,%5,%6,%7}, {%8,%9}, {%0,%1,%2,%3};"
        : "+f"(c[0]), "+f"(c[1]), "+f"(c[2]), "+f"(c[3])
        : "r"(a0), "r"(a1), "r"(a2), "r"(a3), "r"(b0), "r"(b1));
}

__device__ __forceinline__ void cp16(uint32_t dst, const void* src) {
    asm volatile("cp.async.cg.shared.global [%0], [%1], 16;" :: "r"(dst), "l"(src));
}
#define CP_COMMIT() asm volatile("cp.async.commit_group;" ::: "memory")
#define CP_WAIT2()  asm volatile("cp.async.wait_group 2;" ::: "memory")
#define CP_WAIT1()  asm volatile("cp.async.wait_group 1;" ::: "memory")

// ===========================================================================
// GEMM A: 128x128x512, 256 threads, 3-stage (proven R15 path, used by qkv)
// ===========================================================================
constexpr int STG_H = 9216;                       // halves per operand stage
constexpr uint32_t SMEM_QKV = 6 * STG_H * 2;      // 110592 B

__device__ __forceinline__ void gemm128(const __nv_bfloat16* __restrict__ A,
                                        const __nv_bfloat16* __restrict__ B,
                                        float (&acc)[4][4][4])
{
    extern __shared__ __align__(16) uint16_t smh[];
    const uint32_t sbase = smem_u32(smh);
    const int tid  = threadIdx.x;
    const int lane = tid & 31, wid = tid >> 5;
    const int wr = wid >> 2, wc = wid & 3;
    const int l4 = lane >> 2, l3 = lane & 3;

    auto issue = [&](int s, int c) {
        #pragma unroll
        for (int i = 0; i < 4; ++i) {
            const int seg = tid + i * 256;
            const int row = seg >> 3, sc = (seg & 7) * 8;
            cp16(sbase + (uint32_t)(s * STG_H + row * 72 + sc) * 2,
                 A + (size_t)row * DIMC + c * 64 + sc);
            cp16(sbase + (uint32_t)((3 + s) * STG_H + row * 72 + sc) * 2,
                 B + (size_t)row * DIMC + c * 64 + sc);
        }
    };

    issue(0, 0); CP_COMMIT();
    issue(1, 1); CP_COMMIT();
    issue(2, 2); CP_COMMIT();

    int s = 0;
    for (int c = 0; c < 8; ++c) {
        CP_WAIT2();
        __syncthreads();
        const uint32_t* Aw = reinterpret_cast<const uint32_t*>(smh + s * STG_H);
        const uint32_t* Bw = reinterpret_cast<const uint32_t*>(smh + (3 + s) * STG_H);
        #pragma unroll
        for (int ks = 0; ks < 4; ++ks) {
            const int kw = ks * 8;
            uint32_t bf[4][2];
            #pragma unroll
            for (int nt = 0; nt < 4; ++nt) {
                const int base = (wc * 32 + nt * 8 + l4) * 36 + kw + l3;
                bf[nt][0] = Bw[base];
                bf[nt][1] = Bw[base + 4];
            }
            #pragma unroll
            for (int mt = 0; mt < 4; ++mt) {
                const int base = (wr * 64 + mt * 16 + l4) * 36 + kw + l3;
                const uint32_t a0 = Aw[base],     a1 = Aw[base + 288];
                const uint32_t a2 = Aw[base + 4], a3 = Aw[base + 292];
                #pragma unroll
                for (int nt = 0; nt < 4; ++nt)
                    mma16(acc[mt][nt], a0, a1, a2, a3, bf[nt][0], bf[nt][1]);
            }
        }
        __syncthreads();
        if (c + 3 < 8) issue(s, c + 3);
        CP_COMMIT();
        s = (s == 2) ? 0 : s + 1;
    }
}

// ===========================================================================
// GEMM B: 64x512x512 strip, 512 threads (16 warps: 2m x 8n), 2-stage.
// A: [64 x 512] bf16 row-major. B: [512 n x 512 k] bf16 n-major.
// acc[2][8][4]: rows wr*32+mt*16+l4 (+8), cols wc*64+nt*8+2*l3 (+1).
// ===========================================================================
constexpr int A64_H = 64 * 72;                     // 4608 halves
constexpr int B64_H = 512 * 72;                    // 36864 halves
constexpr int STAGE64_H = A64_H + B64_H;           // 41472 halves
constexpr uint32_t SMEM_ATT = 2 * STAGE64_H * 2;   // 165888 B

__device__ __forceinline__ void gemm64(const __nv_bfloat16* __restrict__ A,
                                       const __nv_bfloat16* __restrict__ B,
                                       float (&acc)[2][8][4])
{
    extern __shared__ __align__(16) uint16_t smh[];
    const uint32_t sbase = smem_u32(smh);
    const int tid  = threadIdx.x;
    const int lane = tid & 31, wid = tid >> 5;
    const int wr = wid >> 3, wc = wid & 7;
    const int l4 = lane >> 2, l3 = lane & 3;

    auto issue = [&](int s, int c) {
        {   // A: 512 segs of 16B, one per thread
            const int row = tid >> 3, sc = (tid & 7) * 8;
            cp16(sbase + (uint32_t)(s * STAGE64_H + row * 72 + sc) * 2,
                 A + (size_t)row * DIMC + c * 64 + sc);
        }
        #pragma unroll
        for (int i = 0; i < 8; ++i) {  // B: 4096 segs, 8 per thread
            const int seg = tid + i * 512;
            const int row = seg >> 3, sc = (seg & 7) * 8;
            cp16(sbase + (uint32_t)(s * STAGE64_H + A64_H + row * 72 + sc) * 2,
                 B + (size_t)row * DIMC + c * 64 + sc);
        }
    };

    issue(0, 0); CP_COMMIT();
    issue(1, 1); CP_COMMIT();

    int s = 0;
    for (int c = 0; c < 8; ++c) {
        CP_WAIT1();
        __syncthreads();
        const uint32_t* Aw = reinterpret_cast<const uint32_t*>(smh + s * STAGE64_H);
        const uint32_t* Bw = reinterpret_cast<const uint32_t*>(smh + s * STAGE64_H + A64_H);
        #pragma unroll
        for (int ks = 0; ks < 4; ++ks) {
            const int kw = ks * 8;
            uint32_t bf[8][2];
            #pragma unroll
            for (int nt = 0; nt < 8; ++nt) {
                const int base = (wc * 64 + nt * 8 + l4) * 36 + kw + l3;
                bf[nt][0] = Bw[base];
                bf[nt][1] = Bw[base + 4];
            }
            #pragma unroll
            for (int mt = 0; mt < 2; ++mt) {
                const int base = (wr * 32 + mt * 16 + l4) * 36 + kw + l3;
                const uint32_t a0 = Aw[base],     a1 = Aw[base + 288];
                const uint32_t a2 = Aw[base + 4], a3 = Aw[base + 292];
                #pragma unroll
                for (int nt = 0; nt < 8; ++nt)
                    mma16(acc[mt][nt], a0, a1, a2, a3, bf[nt][0], bf[nt][1]);
            }
        }
        __syncthreads();
        if (c + 2 < 8) issue(s, c + 2);
        CP_COMMIT();
        s ^= 1;
    }
}

// ---------------------------------------------------------------------------
// K0: X -> g_X bf16 ; W{1,2,3} -> g_Wt transposed bf16.
// ---------------------------------------------------------------------------
__global__ __launch_bounds__(256)
void cvt_kernel(const float* __restrict__ X,
                const float* __restrict__ W1, const float* __restrict__ W2,
                const float* __restrict__ W3)
{
    const int NX4 = ROWS * DIMC / 4;
    const int NW4 = DIMC * DIMC / 4;
    const int i = blockIdx.x * blockDim.x + threadIdx.x;
    if (i < NX4) {
        float4 v = reinterpret_cast<const float4*>(X)[i];
        *reinterpret_cast<__nv_bfloat162*>(g_X + (size_t)4 * i)     = __floats2bfloat162_rn(v.x, v.y);
        *reinterpret_cast<__nv_bfloat162*>(g_X + (size_t)4 * i + 2) = __floats2bfloat162_rn(v.z, v.w);
    } else if (i < NX4 + 3 * NW4) {
        int j = i - NX4;
        const int w = j / NW4; j -= w * NW4;
        const int k = j >> 7, n4 = (j & 127) * 4;
        const float* W = (w == 0) ? W1 : (w == 1) ? W2 : W3;
        float4 v = *reinterpret_cast<const float4*>(W + (size_t)k * DIMC + n4);
        g_Wt[w][(size_t)(n4 + 0) * DIMC + k] = __float2bfloat16(v.x);
        g_Wt[w][(size_t)(n4 + 1) * DIMC + k] = __float2bfloat16(v.y);
        g_Wt[w][(size_t)(n4 + 2) * DIMC + k] = __float2bfloat16(v.z);
        g_Wt[w][(size_t)(n4 + 3) * DIMC + k] = __float2bfloat16(v.w);
    }
}

// ---------------------------------------------------------------------------
// K1: Q/K/V = X @ W + b. grid=(4,256,3), 256 thr.
// z<2 -> row-major bf16 Q/K.  z==2 -> V^T via smem transpose (stride 136).
// ---------------------------------------------------------------------------
__global__ __launch_bounds__(256, 2)
void qkv_kernel(const float* __restrict__ B1, const float* __restrict__ B2,
                const float* __restrict__ B3)
{
    const int z = blockIdx.z;
    const int row0 = blockIdx.y * 128;
    const int col0 = blockIdx.x * 128;
    const float* bias = (z == 0) ? B1 : (z == 1) ? B2 : B3;

    float acc[4][4][4] = {};
    gemm128(g_X + (size_t)row0 * DIMC, g_Wt[z] + (size_t)col0 * DIMC, acc);

    const int lane = threadIdx.x & 31, wid = threadIdx.x >> 5;
    const int wr = wid >> 2, wc = wid & 3;
    const int l4 = lane >> 2, l3 = lane & 3;

    if (z < 2) {
        __nv_bfloat16* C = (z == 0) ? g_Qb : g_Kb;
        #pragma unroll
        for (int mt = 0; mt < 4; ++mt) {
            const int row = row0 + wr * 64 + mt * 16 + l4;
            #pragma unroll
            for (int nt = 0; nt < 4; ++nt) {
                const int col = col0 + wc * 32 + nt * 8 + 2 * l3;
                float2 bv = *reinterpret_cast<const float2*>(bias + col);
                __nv_bfloat162 v0 = __floats2bfloat162_rn(acc[mt][nt][0] + bv.x, acc[mt][nt][1] + bv.y);
                __nv_bfloat162 v1 = __floats2bfloat162_rn(acc[mt][nt][2] + bv.x, acc[mt][nt][3] + bv.y);
                *reinterpret_cast<__nv_bfloat162*>(C + (size_t)row * DIMC + col)       = v0;
                *reinterpret_cast<__nv_bfloat162*>(C + (size_t)(row + 8) * DIMC + col) = v1;
            }
        }
    } else {
        extern __shared__ __align__(16) uint16_t smh[];
        __syncthreads();   // pipeline smem dead; reuse as 128x136-half tile
        #pragma unroll
        for (int mt = 0; mt < 4; ++mt) {
            const int r = wr * 64 + mt * 16 + l4;
            #pragma unroll
            for (int nt = 0; nt < 4; ++nt) {
                const int cl = wc * 32 + nt * 8 + 2 * l3;
                float2 bv = *reinterpret_cast<const float2*>(bias + col0 + cl);
                __nv_bfloat162 v0 = __floats2bfloat162_rn(acc[mt][nt][0] + bv.x, acc[mt][nt][1] + bv.y);
                __nv_bfloat162 v1 = __floats2bfloat162_rn(acc[mt][nt][2] + bv.x, acc[mt][nt][3] + bv.y);
                *reinterpret_cast<__nv_bfloat162*>(smh + (size_t)r * 136 + cl)       = v0;
                *reinterpret_cast<__nv_bfloat162*>(smh + (size_t)(r + 8) * 136 + cl) = v1;
            }
        }
        __syncthreads();
        const int tid = threadIdx.x;
        const int d = tid & 127, half = tid >> 7;
        const int bn = row0 >> 9, seq0 = row0 & 511;
        __nv_bfloat16* dst = g_Vt + ((size_t)(bn * DIMC + col0 + d)) * DIMC + seq0 + half * 64;
        #pragma unroll
        for (int i = 0; i < 8; ++i) {
            uint16_t tmp[8];
            #pragma unroll
            for (int j = 0; j < 8; ++j)
                tmp[j] = smh[(size_t)(half * 64 + i * 8 + j) * 136 + d];
            *reinterpret_cast<uint4*>(dst + i * 8) = *reinterpret_cast<const uint4*>(tmp);
        }
    }
}

// ---------------------------------------------------------------------------
// K2 (fused): S = (Q K^T)*scale + mask; row softmax; write P bf16.
// grid=(8, 64), 512 thr. CTA = 64 q rows x full 512 k.
// ---------------------------------------------------------------------------
__global__ __launch_bounds__(512, 1)
void attn_sm_kernel(const float* __restrict__ mask)
{
    const int bn = blockIdx.y;
    const int q0 = blockIdx.x * 64;

    float acc[2][8][4] = {};
    gemm64(g_Qb + (size_t)bn * BLK_ELEMS + (size_t)q0 * DIMC,
           g_Kb + (size_t)bn * BLK_ELEMS, acc);

    const int lane = threadIdx.x & 31, wid = threadIdx.x >> 5;
    const int wr = wid >> 3, wc = wid & 7;
    const int l4 = lane >> 2, l3 = lane & 3;
    __shared__ float red[64][8];
    const float scale = 0.04419417382415922f;  // 1/sqrt(512)

    // mask + scale (overwrite acc), track per-thread row maxima
    float rmax[2][2] = {{-3.4e38f, -3.4e38f}, {-3.4e38f, -3.4e38f}};
    #pragma unroll
    for (int mt = 0; mt < 2; ++mt) {
        const int rl = wr * 32 + mt * 16 + l4;          // local row (lo)
        const size_t grl = (size_t)(bn * DIMC + q0 + rl) * DIMC;
        const size_t grh = grl + (size_t)8 * DIMC;
        #pragma unroll
        for (int nt = 0; nt < 8; ++nt) {
            const int col = wc * 64 + nt * 8 + 2 * l3;
            float2 m0 = *reinterpret_cast<const float2*>(mask + grl + col);
            float2 m1 = *reinterpret_cast<const float2*>(mask + grh + col);
            float s0 = acc[mt][nt][0] * scale + (1.0f - m0.x) * (-1e10f);
            float s1 = acc[mt][nt][1] * scale + (1.0f - m0.y) * (-1e10f);
            float s2 = acc[mt][nt][2] * scale + (1.0f - m1.x) * (-1e10f);
            float s3 = acc[mt][nt][3] * scale + (1.0f - m1.y) * (-1e10f);
            acc[mt][nt][0] = s0; acc[mt][nt][1] = s1;
            acc[mt][nt][2] = s2; acc[mt][nt][3] = s3;
            rmax[mt][0] = fmaxf(rmax[mt][0], fmaxf(s0, s1));
            rmax[mt][1] = fmaxf(rmax[mt][1], fmaxf(s2, s3));
        }
    }
    #pragma unroll
    for (int mt = 0; mt < 2; ++mt)
        #pragma unroll
        for (int h = 0; h < 2; ++h) {
            float v = rmax[mt][h];
            v = fmaxf(v, __shfl_xor_sync(0xffffffffu, v, 1));
            v = fmaxf(v, __shfl_xor_sync(0xffffffffu, v, 2));
            rmax[mt][h] = v;
        }
    if (l3 == 0) {
        #pragma unroll
        for (int mt = 0; mt < 2; ++mt) {
            red[wr * 32 + mt * 16 + l4][wc]     = rmax[mt][0];
            red[wr * 32 + mt * 16 + l4 + 8][wc] = rmax[mt][1];
        }
    }
    __syncthreads();
    float mx[2][2];
    #pragma unroll
    for (int mt = 0; mt < 2; ++mt)
        #pragma unroll
        for (int h = 0; h < 2; ++h) {
            const float* p = red[wr * 32 + mt * 16 + l4 + h * 8];
            float v = fmaxf(fmaxf(p[0], p[1]), fmaxf(p[2], p[3]));
            mx[mt][h] = fmaxf(v, fmaxf(fmaxf(p[4], p[5]), fmaxf(p[6], p[7])));
        }

    // exp (overwrite acc) + row sums
    float rs[2][2] = {{0.f, 0.f}, {0.f, 0.f}};
    #pragma unroll
    for (int mt = 0; mt < 2; ++mt)
        #pragma unroll
        for (int nt = 0; nt < 8; ++nt) {
            float e0 = __expf(acc[mt][nt][0] - mx[mt][0]);
            float e1 = __expf(acc[mt][nt][1] - mx[mt][0]);
            float e2 = __expf(acc[mt][nt][2] - mx[mt][1]);
            float e3 = __expf(acc[mt][nt][3] - mx[mt][1]);
            acc[mt][nt][0] = e0; acc[mt][nt][1] = e1;
            acc[mt][nt][2] = e2; acc[mt][nt][3] = e3;
            rs[mt][0] += e0 + e1;
            rs[mt][1] += e2 + e3;
        }
    #pragma unroll
    for (int mt = 0; mt < 2; ++mt)
        #pragma unroll
        for (int h = 0; h < 2; ++h) {
            float v = rs[mt][h];
            v += __shfl_xor_sync(0xffffffffu, v, 1);
            v += __shfl_xor_sync(0xffffffffu, v, 2);
            rs[mt][h] = v;
        }
    __syncthreads();   // done reading max partials
    if (l3 == 0) {
        #pragma unroll
        for (int mt = 0; mt < 2; ++mt) {
            red[wr * 32 + mt * 16 + l4][wc]     = rs[mt][0];
            red[wr * 32 + mt * 16 + l4 + 8][wc] = rs[mt][1];
        }
    }
    __syncthreads();
    float inv[2][2];
    #pragma unroll
    for (int mt = 0; mt < 2; ++mt)
        #pragma unroll
        for (int h = 0; h < 2; ++h) {
            const float* p = red[wr * 32 + mt * 16 + l4 + h * 8];
            inv[mt][h] = 1.0f / (p[0] + p[1] + p[2] + p[3] + p[4] + p[5] + p[6] + p[7]);
        }

    // write P bf16
    #pragma unroll
    for (int mt = 0; mt < 2; ++mt) {
        const int rl = wr * 32 + mt * 16 + l4;
        const size_t grl = (size_t)(bn * DIMC + q0 + rl) * DIMC;
        const size_t grh = grl + (size_t)8 * DIMC;
        #pragma unroll
        for (int nt = 0; nt < 8; ++nt) {
            const int col = wc * 64 + nt * 8 + 2 * l3;
            __nv_bfloat162 p0 = __floats2bfloat162_rn(acc[mt][nt][0] * inv[mt][0],
                                                      acc[mt][nt][1] * inv[mt][0]);
            __nv_bfloat162 p1 = __floats2bfloat162_rn(acc[mt][nt][2] * inv[mt][1],
                                                      acc[mt][nt][3] * inv[mt][1]);
            *reinterpret_cast<__nv_bfloat162*>(g_P + grl + col) = p0;
            *reinterpret_cast<__nv_bfloat162*>(g_P + grh + col) = p1;
        }
    }
}

// ---------------------------------------------------------------------------
// K3 (fused): O = P V + X; LayerNorm(eps=1e-3); write d_out.
// grid=(8, 64), 512 thr. CTA = 64 rows x full 512 d.
// ---------------------------------------------------------------------------
__global__ __launch_bounds__(512, 1)
void attn_out_kernel(const float* __restrict__ X, float* __restrict__ out)
{
    const int bn = blockIdx.y;
    const int q0 = blockIdx.x * 64;

    float acc[2][8][4] = {};
    gemm64(g_P  + (size_t)bn * BLK_ELEMS + (size_t)q0 * DIMC,
           g_Vt + (size_t)bn * BLK_ELEMS, acc);

    const int lane = threadIdx.x & 31, wid = threadIdx.x >> 5;
    const int wr = wid >> 3, wc = wid & 7;
    const int l4 = lane >> 2, l3 = lane & 3;
    __shared__ float red[64][8];

    // residual (overwrite acc) + row sums
    float rs[2][2] = {{0.f, 0.f}, {0.f, 0.f}};
    #pragma unroll
    for (int mt = 0; mt < 2; ++mt) {
        const int rl = wr * 32 + mt * 16 + l4;
        const size_t grl = (size_t)(bn * DIMC + q0 + rl) * DIMC;
        const size_t grh = grl + (size_t)8 * DIMC;
        #pragma unroll
        for (int nt = 0; nt < 8; ++nt) {
            const int col = wc * 64 + nt * 8 + 2 * l3;
            float2 x0 = *reinterpret_cast<const float2*>(X + grl + col);
            float2 x1 = *reinterpret_cast<const float2*>(X + grh + col);
            float o0 = acc[mt][nt][0] + x0.x, o1 = acc[mt][nt][1] + x0.y;
            float o2 = acc[mt][nt][2] + x1.x, o3 = acc[mt][nt][3] + x1.y;
            acc[mt][nt][0] = o0; acc[mt][nt][1] = o1;
            acc[mt][nt][2] = o2; acc[mt][nt][3] = o3;
            rs[mt][0] += o0 + o1;
            rs[mt][1] += o2 + o3;
        }
    }
    #pragma unroll
    for (int mt = 0; mt < 2; ++mt)
        #pragma unroll
        for (int h = 0; h < 2; ++h) {
            float v = rs[mt][h];
            v += __shfl_xor_sync(0xffffffffu, v, 1);
            v += __shfl_xor_sync(0xffffffffu, v, 2);
            rs[mt][h] = v;
        }
    if (l3 == 0) {
        #pragma unroll
        for (int mt = 0; mt < 2; ++mt) {
            red[wr * 32 + mt * 16 + l4][wc]     = rs[mt][0];
            red[wr * 32 + mt * 16 + l4 + 8][wc] = rs[mt][1];
        }
    }
    __syncthreads();
    float mean[2][2];
    #pragma unroll
    for (int mt = 0; mt < 2; ++mt)
        #pragma unroll
        for (int h = 0; h < 2; ++h) {
            const float* p = red[wr * 32 + mt * 16 + l4 + h * 8];
            mean[mt][h] = (p[0] + p[1] + p[2] + p[3] + p[4] + p[5] + p[6] + p[7]) * (1.0f / 512.0f);
        }

    // centered sum of squares
    float rq[2][2] = {{0.f, 0.f}, {0.f, 0.f}};
    #pragma unroll
    for (int mt = 0; mt < 2; ++mt)
        #pragma unroll
        for (int nt = 0; nt < 8; ++nt) {
            float d0 = acc[mt][nt][0] - mean[mt][0];
            float d1 = acc[mt][nt][1] - mean[mt][0];
            float d2 = acc[mt][nt][2] - mean[mt][1];
            float d3 = acc[mt][nt][3] - mean[mt][1];
            rq[mt][0] += d0 * d0 + d1 * d1;
            rq[mt][1] += d2 * d2 + d3 * d3;
        }
    #pragma unroll
    for (int mt = 0; mt < 2; ++mt)
        #pragma unroll
        for (int h = 0; h < 2; ++h) {
            float v = rq[mt][h];
            v += __shfl_xor_sync(0xffffffffu, v, 1);
            v += __shfl_xor_sync(0xffffffffu, v, 2);
            rq[mt][h] = v;
        }
    __syncthreads();   // done reading mean partials
    if (l3 == 0) {
        #pragma unroll
        for (int mt = 0; mt < 2; ++mt) {
            red[wr * 32 + mt * 16 + l4][wc]     = rq[mt][0];
            red[wr * 32 + mt * 16 + l4 + 8][wc] = rq[mt][1];
        }
    }
    __syncthreads();
    float inv[2][2];
    #pragma unroll
    for (int mt = 0; mt < 2; ++mt)
        #pragma unroll
        for (int h = 0; h < 2; ++h) {
            const float* p = red[wr * 32 + mt * 16 + l4 + h * 8];
            float var = (p[0] + p[1] + p[2] + p[3] + p[4] + p[5] + p[6] + p[7]) * (1.0f / 512.0f);
            inv[mt][h] = rsqrtf(var + 1e-3f);
        }

    // write normalized output
    #pragma unroll
    for (int mt = 0; mt < 2; ++mt) {
        const int rl = wr * 32 + mt * 16 + l4;
        const size_t grl = (size_t)(bn * DIMC + q0 + rl) * DIMC;
        const size_t grh = grl + (size_t)8 * DIMC;
        #pragma unroll
        for (int nt = 0; nt < 8; ++nt) {
            const int col = wc * 64 + nt * 8 + 2 * l3;
            float2 v0 = { (acc[mt][nt][0] - mean[mt][0]) * inv[mt][0],
                          (acc[mt][nt][1] - mean[mt][0]) * inv[mt][0] };
            float2 v1 = { (acc[mt][nt][2] - mean[mt][1]) * inv[mt][1],
                          (acc[mt][nt][3] - mean[mt][1]) * inv[mt][1] };
            *reinterpret_cast<float2*>(out + grl + col) = v0;
            *reinterpret_cast<float2*>(out + grh + col) = v1;
        }
    }
}

// ---------------------------------------------------------------------------
extern "C" void kernel_launch(void* const* d_in, const int* in_sizes, int n_in,
                              void* d_out, int out_size)
{
    const float* X    = (const float*)d_in[0];
    const float* mask = (const float*)d_in[1];
    const float* w1   = (const float*)d_in[2];
    const float* w2   = (const float*)d_in[3];
    const float* w3   = (const float*)d_in[4];
    const float* b1   = (const float*)d_in[5];
    const float* b2   = (const float*)d_in[6];
    const float* b3   = (const float*)d_in[7];
    float* out        = (float*)d_out;

    // Unconditional, idempotent (no static guards per harness rules).
    cudaFuncSetAttribute(qkv_kernel,      cudaFuncAttributeMaxDynamicSharedMemorySize, SMEM_QKV);
    cudaFuncSetAttribute(attn_sm_kernel,  cudaFuncAttributeMaxDynamicSharedMemorySize, SMEM_ATT);
    cudaFuncSetAttribute(attn_out_kernel, cudaFuncAttributeMaxDynamicSharedMemorySize, SMEM_ATT);

    const int NCVT = ROWS * DIMC / 4 + 3 * DIMC * DIMC / 4;
    cvt_kernel<<<(NCVT + 255) / 256, 256>>>(X, w1, w2, w3);
    qkv_kernel<<<dim3(4, 256, 3), 256, SMEM_QKV>>>(b1, b2, b3);
    attn_sm_kernel<<<dim3(8, 64), 512, SMEM_ATT>>>(mask);
    attn_out_kernel<<<dim3(8, 64), 512, SMEM_ATT>>>(X, out);
}